// round 9
// baseline (speedup 1.0000x reference)
#include <cuda_runtime.h>
#include <math.h>
#include <stdint.h>

#define B_  8
#define L_  2048
#define E_  100
#define FM_ 50
#define Y_  8921
#define K_  9

#define TY  32          // labels per block (attn kernel): 8 warps x 4 labels
#define LC  128         // l-chunk staged in smem (shared by all warps)
#define NCH (L_ / LC)   // 16 chunks
#define NYT 279         // ceil(Y_/TY)
#define WROW (TY / 2)   // one f-row of dup-packed weights, in 16-byte units (=16)

// scratch (static device arrays are allowed)
__device__ float g_h[(size_t)B_ * FM_ * L_];          // [b][f][l]  3.28 MB
__device__ float g_losspart[B_ * NYT];

// ---- packed f32x2 helpers ------------------------------------------------
__device__ __forceinline__ float2 unpack2(unsigned long long v) {
    float2 f;
    asm("mov.b64 {%0,%1}, %2;" : "=f"(f.x), "=f"(f.y) : "l"(v));
    return f;
}
#define FMA2(d, a, b) \
    asm("fma.rn.f32x2 %0, %1, %2, %0;" : "+l"(d) : "l"(a), "l"(b))

// ---- cp.async helpers ------------------------------------------------------
__device__ __forceinline__ void cp_async16(uint32_t dst_smem, const void* src) {
    asm volatile("cp.async.cg.shared.global [%0], [%1], 16;"
                 :: "r"(dst_smem), "l"(src));
}
#define CP_COMMIT() asm volatile("cp.async.commit_group;" ::: "memory")
#define CP_WAIT1()  asm volatile("cp.async.wait_group 1;"  ::: "memory")

// ---------------------------------------------------------------------------
// Kernel 1: embedding gather + conv1d(K=9, same) + bias + tanh -> g_h[b][f][l]
// ---------------------------------------------------------------------------
__global__ void __launch_bounds__(256) conv_kernel(
    const int* __restrict__ tokens,
    const float* __restrict__ embed_W,
    const float* __restrict__ conv_w,
    const float* __restrict__ conv_b)
{
    __shared__ int   tok_s[72];
    __shared__ float x_s[72][21];          // e-chunk of 20 (pad 21)
    __shared__ float w_s[50][20][9];       // f, e-chunk, k

    const int tid   = threadIdx.x;
    const int b     = blockIdx.y;
    const int lbase = blockIdx.x * 64;

    if (tid < 72) {
        int gl = lbase + tid - 4;
        tok_s[tid] = (gl >= 0 && gl < L_) ? tokens[b * L_ + gl] : -1;
    }
    __syncthreads();

    const int f  = tid >> 2;     // 0..63 (valid < 50)
    const int lg = tid & 3;
    const int l0 = lg * 16;

    float acc[16];
#pragma unroll
    for (int j = 0; j < 16; j++) acc[j] = 0.f;

    for (int ec = 0; ec < 5; ec++) {
        for (int idx = tid; idx < 72 * 20; idx += 256) {
            int i = idx / 20, e = idx % 20;
            int t = tok_s[i];
            x_s[i][e] = (t >= 0) ? embed_W[(size_t)t * E_ + ec * 20 + e] : 0.f;
        }
        for (int idx = tid; idx < 50 * 20 * 9; idx += 256) {
            int ff = idx / 180, r = idx % 180;
            w_s[ff][r / 9][r % 9] = conv_w[ff * (E_ * K_) + ec * 180 + r];
        }
        __syncthreads();

        if (f < FM_) {
            for (int e = 0; e < 20; e++) {
                float xv[24];
#pragma unroll
                for (int t = 0; t < 24; t++) xv[t] = x_s[l0 + t][e];
                float wv[9];
#pragma unroll
                for (int k = 0; k < 9; k++) wv[k] = w_s[f][e][k];
#pragma unroll
                for (int k = 0; k < 9; k++)
#pragma unroll
                    for (int j = 0; j < 16; j++)
                        acc[j] += xv[j + k] * wv[k];
            }
        }
        __syncthreads();
    }

    if (f < FM_) {
        float bias = conv_b[f];
#pragma unroll
        for (int j = 0; j < 16; j++) {
            int l = lbase + l0 + j;
            g_h[((size_t)(b * FM_) + f) * L_ + l] = tanhf(acc[j] + bias);
        }
    }
}

// ---------------------------------------------------------------------------
// Kernel 2: fused label-attention with cp.async double-buffered h staging.
// block = (y-tile of 32, b), 256 threads = 8 warps, 2 CTAs/SM.
// ALL warps share the same 128-position chunk; warp w owns labels 4w..4w+3.
// Weight layout: u_d4[f*WROW + j] = {u[2j],u[2j],u[2j+1],u[2j+1]}, WROW=16.
// Pipeline: chunk ch+1 streams into buf[(ch+1)&1] via cp.async while ch is
// computed from buf[ch&1]; wait_group(1) + barrier make it visible.
// ---------------------------------------------------------------------------
__global__ void __launch_bounds__(256, 2) attn_kernel(
    const float* __restrict__ U_w,
    const float* __restrict__ final_w,
    const float* __restrict__ final_b,
    const float* __restrict__ target,
    float* __restrict__ out_yhat,
    float* __restrict__ out_alpha,
    int write_alpha)
{
    extern __shared__ __align__(16) unsigned char smraw[];
    float*  h_s    = (float*)smraw;                    // 2 * FM_*LC  (51.2 KB)
    float4* u_d4   = (float4*)(h_s + 2 * FM_ * LC);    // FM_*WROW    (12.8 KB)
    float4* f_d4   = u_d4 + FM_ * WROW;                // FM_*WROW    (12.8 KB)
    float*  loss_s = (float*)(f_d4 + FM_ * WROW);      // 8

    const int tid  = threadIdx.x;
    const int lane = tid & 31;
    const int warp = tid >> 5;
    const int b    = blockIdx.y;
    const int y0t  = blockIdx.x * TY;

    const int yl0   = warp * 4;       // warp's first label within tile
    const int pbase = 2 * lane;       // position base within 128-chunk

    const uint32_t h_s_u32 =
        (uint32_t)__cvta_generic_to_shared(h_s);
    const float4* gh4 = (const float4*)(g_h + (size_t)b * FM_ * L_);

    // prologue: start staging chunk 0 into buffer 0 (cp.async, no reg traffic)
    {
#pragma unroll
        for (int idx = tid; idx < FM_ * LC / 4; idx += 256) {
            int f = idx >> 5, v = idx & 31;
            cp_async16(h_s_u32 + (uint32_t)(((f << 5) + v) * 16),
                       gh4 + (size_t)f * (L_ / 4) + v);
        }
        CP_COMMIT();
    }

    // stage duplicated weights: u_d4[f*WROW+j] = {u[2j],u[2j],u[2j+1],u[2j+1]}
    for (int idx = tid; idx < FM_ * WROW; idx += 256) {
        int f = idx / WROW, j = idx % WROW;
        int gy0 = y0t + 2 * j, gy1 = gy0 + 1;
        float u0 = (gy0 < Y_) ? U_w[gy0 * FM_ + f] : 0.f;
        float u1 = (gy1 < Y_) ? U_w[gy1 * FM_ + f] : 0.f;
        u_d4[idx] = make_float4(u0, u0, u1, u1);
        float v0 = (gy0 < Y_) ? final_w[gy0 * FM_ + f] : 0.f;
        float v1 = (gy1 < Y_) ? final_w[gy1 * FM_ + f] : 0.f;
        f_d4[idx] = make_float4(v0, v0, v1, v1);
    }

    float Zacc[4] = {0.f, 0.f, 0.f, 0.f};
    float Racc[4] = {0.f, 0.f, 0.f, 0.f};

    const size_t arow = (size_t)b * Y_ + y0t;   // first label row of this block

    for (int ch = 0; ch < NCH; ch++) {
        // stage next chunk into the other buffer. Safe WAR: that buffer's
        // readers (compute of ch-1) all passed the barrier at end of ch-1.
        if (ch + 1 < NCH) {
            const uint32_t dstb =
                h_s_u32 + (uint32_t)(((ch + 1) & 1) * FM_ * LC * 4);
            const float4* gsrc = gh4 + ((ch + 1) * LC) / 4;
#pragma unroll
            for (int idx = tid; idx < FM_ * LC / 4; idx += 256) {
                int f = idx >> 5, v = idx & 31;
                cp_async16(dstb + (uint32_t)(((f << 5) + v) * 16),
                           gsrc + (size_t)f * (L_ / 4) + v);
            }
        }
        CP_COMMIT();          // always commit (possibly empty group)
        CP_WAIT1();           // all but newest group done => chunk ch staged
        __syncthreads();      // cross-thread visibility of staged chunk ch

        const int   lb    = ch * LC;
        const float* hbuf = h_s + (ch & 1) * FM_ * LC;

        unsigned long long S[4][2] = {{0,0},{0,0},{0,0},{0,0}};
        unsigned long long Q[4][2] = {{0,0},{0,0},{0,0},{0,0}};

        const float*      hp = hbuf + pbase;
        // warp's 2 entries within each f-row; advance by WROW entries per f
        const ulonglong2* up = (const ulonglong2*)(u_d4) + warp * 2;
        const ulonglong2* fp = (const ulonglong2*)(f_d4) + warp * 2;

#pragma unroll 2
        for (int f = 0; f < FM_; f++) {
            unsigned long long h0 = *(const unsigned long long*)(hp);
            unsigned long long h1 = *(const unsigned long long*)(hp + 64);
            ulonglong2 ua = up[0];   // labels yl0, yl0+1 (dup-packed)
            ulonglong2 ub = up[1];   // labels yl0+2, yl0+3
            ulonglong2 fa = fp[0];
            ulonglong2 fb = fp[1];
            FMA2(S[0][0], h0, ua.x); FMA2(S[0][1], h1, ua.x);
            FMA2(S[1][0], h0, ua.y); FMA2(S[1][1], h1, ua.y);
            FMA2(S[2][0], h0, ub.x); FMA2(S[2][1], h1, ub.x);
            FMA2(S[3][0], h0, ub.y); FMA2(S[3][1], h1, ub.y);
            FMA2(Q[0][0], h0, fa.x); FMA2(Q[0][1], h1, fa.x);
            FMA2(Q[1][0], h0, fa.y); FMA2(Q[1][1], h1, fa.y);
            FMA2(Q[2][0], h0, fb.x); FMA2(Q[2][1], h1, fb.x);
            FMA2(Q[3][0], h0, fb.y); FMA2(Q[3][1], h1, fb.y);
            hp += LC; up += WROW; fp += WROW;
        }

        // per-chunk epilogue: e = exp(s) -> gmem (unnormalized, SCALAR stores)
#pragma unroll
        for (int i = 0; i < 4; i++) {
            const int gy = y0t + yl0 + i;
            float* abase = out_alpha + (arow + yl0 + i) * L_ + lb + pbase;
#pragma unroll
            for (int p = 0; p < 2; p++) {
                float2 s = unpack2(S[i][p]);
                float2 q = unpack2(Q[i][p]);
                float e0 = __expf(s.x), e1 = __expf(s.y);
                Zacc[i] += e0 + e1;
                Racc[i] += e0 * q.x + e1 * q.y;
                if (write_alpha && gy < Y_) {
                    abase[p * 64 + 0] = e0;
                    abase[p * 64 + 1] = e1;
                }
            }
        }

        __syncthreads();      // all warps done reading buf[ch&1]
    }

    // butterfly reduction: every lane ends with full Z,R for the warp's labels
#pragma unroll
    for (int o = 16; o > 0; o >>= 1) {
#pragma unroll
        for (int i = 0; i < 4; i++) {
            Zacc[i] += __shfl_xor_sync(0xffffffffu, Zacc[i], o);
            Racc[i] += __shfl_xor_sync(0xffffffffu, Racc[i], o);
        }
    }

    // yhat + BCE terms for the warp's 4 labels (lane 0)
    if (lane == 0) {
        float lsum = 0.f;
#pragma unroll
        for (int i = 0; i < 4; i++) {
            int gy = y0t + yl0 + i;
            if (gy < Y_) {
                float r  = Racc[i] / Zacc[i] + final_b[gy];
                float yh = 1.f / (1.f + expf(-r));
                out_yhat[b * Y_ + gy] = yh;
                float t = target[b * Y_ + gy];
                lsum += t * logf(yh + 1e-12f) +
                        (1.f - t) * logf(1.f - yh + 1e-12f);
            }
        }
        loss_s[warp] = lsum;
    }

    // in-place rescale of the warp's own 4 alpha rows (L2-hot). No barrier
    // needed: this warp wrote those rows itself. SCALAR accesses (4B align).
    if (write_alpha) {
#pragma unroll
        for (int i = 0; i < 4; i++) {
            int gy = y0t + yl0 + i;
            if (gy >= Y_) continue;
            float iZ = 1.f / Zacc[i];
            float* ap = out_alpha + (arow + yl0 + i) * L_;
#pragma unroll 4
            for (int v = lane; v < L_; v += 32)
                ap[v] *= iZ;
        }
    }

    __syncthreads();
    if (tid == 0) {
        float s = 0.f;
#pragma unroll
        for (int i = 0; i < 8; i++) s += loss_s[i];
        g_losspart[b * gridDim.x + blockIdx.x] = s;
    }
}

// ---------------------------------------------------------------------------
// Kernel 3: deterministic loss reduction
// ---------------------------------------------------------------------------
__global__ void loss_kernel(float* __restrict__ out_loss, int npart)
{
    __shared__ float red[256];
    float s = 0.f;
    for (int i = threadIdx.x; i < npart; i += 256) s += g_losspart[i];
    red[threadIdx.x] = s;
    __syncthreads();
    for (int o = 128; o > 0; o >>= 1) {
        if (threadIdx.x < o) red[threadIdx.x] += red[threadIdx.x + o];
        __syncthreads();
    }
    if (threadIdx.x == 0) *out_loss = -red[0] / (float)(B_ * Y_);
}

// ---------------------------------------------------------------------------
extern "C" void kernel_launch(void* const* d_in, const int* in_sizes, int n_in,
                              void* d_out, int out_size)
{
    const int*   tokens  = (const int*)  d_in[0];
    const float* target  = (const float*)d_in[1];
    const float* embed_W = (const float*)d_in[2];
    const float* conv_w  = (const float*)d_in[3];
    const float* conv_b  = (const float*)d_in[4];
    const float* U_w     = (const float*)d_in[5];
    const float* final_w = (const float*)d_in[6];
    const float* final_b = (const float*)d_in[7];
    float* out = (float*)d_out;

    const long long yhat_n  = (long long)B_ * Y_;                 // 71368
    const long long total_n = yhat_n + 1 + (long long)B_ * Y_ * L_;
    int write_loss  = (out_size >= (int)(yhat_n + 1)) ? 1 : 0;
    int write_alpha = ((long long)out_size >= total_n) ? 1 : 0;

    const int smem_bytes = (2 * FM_ * LC) * 4            // h double buffer
                         + (2 * FM_ * WROW) * 16         // dup-packed weights
                         + 8 * 4;                        // loss_s
    cudaFuncSetAttribute(attn_kernel, cudaFuncAttributeMaxDynamicSharedMemorySize,
                         smem_bytes);

    conv_kernel<<<dim3(L_ / 64, B_), 256>>>(tokens, embed_W, conv_w, conv_b);

    float* out_alpha = out + yhat_n + 1;
    attn_kernel<<<dim3(NYT, B_), 256, smem_bytes>>>(
        U_w, final_w, final_b, target, out, out_alpha, write_alpha);

    if (write_loss)
        loss_kernel<<<1, 256>>>(out + yhat_n, B_ * NYT);
}

// round 10
// speedup vs baseline: 1.2885x; 1.2885x over previous
#include <cuda_runtime.h>
#include <math.h>
#include <stdint.h>

#define B_  8
#define L_  2048
#define E_  100
#define FM_ 50
#define Y_  8921
#define K_  9

#define YT   32          // labels per attn block
#define NYT  279         // ceil(Y_/YT)
#define FP   60          // padded f stride for transposed h (conflict-free LDS)
#define LCH  256         // positions per chunk
#define NCHK (L_ / LCH)  // 8
#define NK   7           // k-steps of 8 covering f 0..55 (50 real + zero pad)

// scratch (static device arrays are allowed)
__device__ float g_h [(size_t)B_ * FM_ * L_];      // conv output [b][f][l]
__device__ float g_ht[(size_t)B_ * L_  * FP];      // transposed  [b][l][60]
__device__ float g_losspart[B_ * NYT];

// ---- tf32 / mma helpers ----------------------------------------------------
__device__ __forceinline__ float tf32_rn(float x) {
    uint32_t r; asm("cvt.rna.tf32.f32 %0, %1;" : "=r"(r) : "f"(x));
    return __uint_as_float(r);
}
__device__ __forceinline__ void mma_tf32(float d[4],
                                         const float a[4],
                                         float b0, float b1) {
    asm("mma.sync.aligned.m16n8k8.row.col.f32.tf32.tf32.f32 "
        "{%0,%1,%2,%3},{%4,%5,%6,%7},{%8,%9},{%0,%1,%2,%3};"
        : "+f"(d[0]), "+f"(d[1]), "+f"(d[2]), "+f"(d[3])
        : "r"(__float_as_uint(a[0])), "r"(__float_as_uint(a[1])),
          "r"(__float_as_uint(a[2])), "r"(__float_as_uint(a[3])),
          "r"(__float_as_uint(b0)),  "r"(__float_as_uint(b1)));
}

// ---------------------------------------------------------------------------
// Kernel 1: embedding gather + conv1d(K=9, same) + bias + tanh -> g_h[b][f][l]
// (unchanged from the proven round-8 kernel)
// ---------------------------------------------------------------------------
__global__ void __launch_bounds__(256) conv_kernel(
    const int* __restrict__ tokens,
    const float* __restrict__ embed_W,
    const float* __restrict__ conv_w,
    const float* __restrict__ conv_b)
{
    __shared__ int   tok_s[72];
    __shared__ float x_s[72][21];
    __shared__ float w_s[50][20][9];

    const int tid   = threadIdx.x;
    const int b     = blockIdx.y;
    const int lbase = blockIdx.x * 64;

    if (tid < 72) {
        int gl = lbase + tid - 4;
        tok_s[tid] = (gl >= 0 && gl < L_) ? tokens[b * L_ + gl] : -1;
    }
    __syncthreads();

    const int f  = tid >> 2;
    const int lg = tid & 3;
    const int l0 = lg * 16;

    float acc[16];
#pragma unroll
    for (int j = 0; j < 16; j++) acc[j] = 0.f;

    for (int ec = 0; ec < 5; ec++) {
        for (int idx = tid; idx < 72 * 20; idx += 256) {
            int i = idx / 20, e = idx % 20;
            int t = tok_s[i];
            x_s[i][e] = (t >= 0) ? embed_W[(size_t)t * E_ + ec * 20 + e] : 0.f;
        }
        for (int idx = tid; idx < 50 * 20 * 9; idx += 256) {
            int ff = idx / 180, r = idx % 180;
            w_s[ff][r / 9][r % 9] = conv_w[ff * (E_ * K_) + ec * 180 + r];
        }
        __syncthreads();

        if (f < FM_) {
            for (int e = 0; e < 20; e++) {
                float xv[24];
#pragma unroll
                for (int t = 0; t < 24; t++) xv[t] = x_s[l0 + t][e];
                float wv[9];
#pragma unroll
                for (int k = 0; k < 9; k++) wv[k] = w_s[f][e][k];
#pragma unroll
                for (int k = 0; k < 9; k++)
#pragma unroll
                    for (int j = 0; j < 16; j++)
                        acc[j] += xv[j + k] * wv[k];
            }
        }
        __syncthreads();
    }

    if (f < FM_) {
        float bias = conv_b[f];
#pragma unroll
        for (int j = 0; j < 16; j++) {
            int l = lbase + l0 + j;
            g_h[((size_t)(b * FM_) + f) * L_ + l] = tanhf(acc[j] + bias);
        }
    }
}

// ---------------------------------------------------------------------------
// Kernel 1b: transpose g_h[b][f][l] -> g_ht[b][l][60], zero-pad f 50..59
// ---------------------------------------------------------------------------
__global__ void __launch_bounds__(256) transpose_kernel()
{
    const int b = blockIdx.y;
    const int l = blockIdx.x * 256 + threadIdx.x;
    float* dst = g_ht + ((size_t)b * L_ + l) * FP;
#pragma unroll 5
    for (int f = 0; f < FM_; f++)
        dst[f] = g_h[((size_t)b * FM_ + f) * L_ + l];
#pragma unroll
    for (int f = FM_; f < FP; f++) dst[f] = 0.f;
}

// ---------------------------------------------------------------------------
// Kernel 2: label attention via 3xTF32 mma.sync (m16n8k8).
// block = (32 labels, b), 256 threads = 8 warps, 2 CTAs/SM.
// Chunk = 256 positions staged in smem; warp w owns positions [32w, 32w+32)
// (2 M-tiles of 16). N = labels: 4 N-tiles of 8 cover the 32 labels.
// Weights pre-split hi/lo into per-lane fragment order (one LDS.128 = full
// B fragment pair). A fragments built from fp32 h with cvt.rna.tf32.
// S and Q each via 3 mma (ah*bh + ah*bl + al*bh), fp32 accumulate.
// Epilogue per chunk: e=exp(s) -> alpha gmem (scalar, label-guarded),
// Z += e, R += e*q lane-locally. Tail: butterfly over g, cross-warp smem
// reduce, yhat/loss, in-place L2-hot rescale (from proven R8 kernel).
// ---------------------------------------------------------------------------
__global__ void __launch_bounds__(256, 2) attn_kernel(
    const float* __restrict__ U_w,
    const float* __restrict__ final_w,
    const float* __restrict__ final_b,
    const float* __restrict__ target,
    float* __restrict__ out_yhat,
    float* __restrict__ out_alpha,
    int write_alpha)
{
    extern __shared__ __align__(16) unsigned char smraw[];
    float4* wS4  = (float4*)smraw;              // [NK*4*32]  14336 B
    float4* wQ4  = wS4 + NK * 4 * 32;           // [NK*4*32]  14336 B
    float*  h_s  = (float*)(wQ4 + NK * 4 * 32); // [LCH*FP]   61440 B
    float*  zs   = h_s + LCH * FP;              // [8*32]
    float*  rs   = zs + 8 * 32;                 // [8*32]
    float*  iZ_s = rs + 8 * 32;                 // [32]
    float*  lt   = iZ_s + YT;                   // [32]

    const int tid  = threadIdx.x;
    const int lane = tid & 31;
    const int warp = tid >> 5;
    const int b    = blockIdx.y;
    const int y0t  = blockIdx.x * YT;

    const int g = lane >> 2;       // mma groupID (0..7)
    const int t = lane & 3;        // mma thread-in-group (0..3)

    // ---- build fragment-order hi/lo weight arrays ----
    // entry (k, nt, ln): B[k-row tt (+4)][n-col gg] = W[label nt*8+gg][f k*8+tt]
    for (int idx = tid; idx < NK * 4 * 32; idx += 256) {
        int k  = idx >> 7;          // /(4*32)
        int nt = (idx >> 5) & 3;
        int ln = idx & 31;
        int gg = ln >> 2, tt = ln & 3;
        int gy = y0t + nt * 8 + gg;
        int f0 = k * 8 + tt, f1 = f0 + 4;
        float u0 = 0.f, u1 = 0.f, v0 = 0.f, v1 = 0.f;
        if (gy < Y_) {
            if (f0 < FM_) { u0 = U_w[gy * FM_ + f0]; v0 = final_w[gy * FM_ + f0]; }
            if (f1 < FM_) { u1 = U_w[gy * FM_ + f1]; v1 = final_w[gy * FM_ + f1]; }
        }
        float uh0 = tf32_rn(u0), uh1 = tf32_rn(u1);
        wS4[idx] = make_float4(uh0, uh1, tf32_rn(u0 - uh0), tf32_rn(u1 - uh1));
        float vh0 = tf32_rn(v0), vh1 = tf32_rn(v1);
        wQ4[idx] = make_float4(vh0, vh1, tf32_rn(v0 - vh0), tf32_rn(v1 - vh1));
    }

    // lane-local Z,R: label = nt*8 + 2t + p
    float Zl[4][2] = {{0.f,0.f},{0.f,0.f},{0.f,0.f},{0.f,0.f}};
    float Rl[4][2] = {{0.f,0.f},{0.f,0.f},{0.f,0.f},{0.f,0.f}};

    const size_t hbase = (size_t)b * L_ * FP;
    const size_t arow0 = (size_t)b * Y_;
    const int prow0 = warp * 32;   // warp's first position row within chunk

    for (int ch = 0; ch < NCHK; ch++) {
        __syncthreads();   // previous chunk readers done (covers weight build)
        {   // stage: contiguous copy of 256 rows x 60 floats
            const float4* src = (const float4*)(g_ht + hbase + (size_t)ch * LCH * FP);
            float4* dst = (float4*)h_s;
            for (int i = tid; i < LCH * FP / 4; i += 256) dst[i] = src[i];
        }
        __syncthreads();

        float accS[2][4][4] = {};
        float accQ[2][4][4] = {};

#pragma unroll
        for (int k = 0; k < NK; k++) {
            // A fragments (h) for the warp's 2 M-tiles, hi/lo split on the fly
            float ahi[2][4], alo[2][4];
#pragma unroll
            for (int mt = 0; mt < 2; mt++) {
                const int r0 = prow0 + mt * 16 + g;
                float x0 = h_s[ r0      * FP + k * 8 + t];
                float x1 = h_s[(r0 + 8) * FP + k * 8 + t];
                float x2 = h_s[ r0      * FP + k * 8 + t + 4];
                float x3 = h_s[(r0 + 8) * FP + k * 8 + t + 4];
                ahi[mt][0] = tf32_rn(x0); alo[mt][0] = tf32_rn(x0 - ahi[mt][0]);
                ahi[mt][1] = tf32_rn(x1); alo[mt][1] = tf32_rn(x1 - ahi[mt][1]);
                ahi[mt][2] = tf32_rn(x2); alo[mt][2] = tf32_rn(x2 - ahi[mt][2]);
                ahi[mt][3] = tf32_rn(x3); alo[mt][3] = tf32_rn(x3 - ahi[mt][3]);
            }
#pragma unroll
            for (int nt = 0; nt < 4; nt++) {
                float4 Bs = wS4[(k * 4 + nt) * 32 + lane];
                float4 Bq = wQ4[(k * 4 + nt) * 32 + lane];
#pragma unroll
                for (int mt = 0; mt < 2; mt++) {
                    mma_tf32(accS[mt][nt], ahi[mt], Bs.x, Bs.y);  // ah*bh
                    mma_tf32(accS[mt][nt], ahi[mt], Bs.z, Bs.w);  // ah*bl
                    mma_tf32(accS[mt][nt], alo[mt], Bs.x, Bs.y);  // al*bh
                    mma_tf32(accQ[mt][nt], ahi[mt], Bq.x, Bq.y);
                    mma_tf32(accQ[mt][nt], ahi[mt], Bq.z, Bq.w);
                    mma_tf32(accQ[mt][nt], alo[mt], Bq.x, Bq.y);
                }
            }
        }

        // per-chunk epilogue: acc layout c0=(g,2t) c1=(g,2t+1) c2=(g+8,2t) c3
        const int chb = ch * LCH;
#pragma unroll
        for (int mt = 0; mt < 2; mt++) {
            const int posA = chb + prow0 + mt * 16 + g;
            const int posB = posA + 8;
#pragma unroll
            for (int nt = 0; nt < 4; nt++) {
                const int lab0 = y0t + nt * 8 + 2 * t;
                const int lab1 = lab0 + 1;
                float e0 = __expf(accS[mt][nt][0]);
                float e1 = __expf(accS[mt][nt][1]);
                float e2 = __expf(accS[mt][nt][2]);
                float e3 = __expf(accS[mt][nt][3]);
                Zl[nt][0] += e0 + e2;
                Zl[nt][1] += e1 + e3;
                Rl[nt][0] += e0 * accQ[mt][nt][0] + e2 * accQ[mt][nt][2];
                Rl[nt][1] += e1 * accQ[mt][nt][1] + e3 * accQ[mt][nt][3];
                if (write_alpha) {
                    if (lab0 < Y_) {
                        float* rp = out_alpha + (arow0 + lab0) * L_;
                        rp[posA] = e0; rp[posB] = e2;
                    }
                    if (lab1 < Y_) {
                        float* rp = out_alpha + (arow0 + lab1) * L_;
                        rp[posA] = e1; rp[posB] = e3;
                    }
                }
            }
        }
    }

    // reduce over g (lane bits 2,3,4) -> lanes 0..3 hold sums for t=lane
#pragma unroll
    for (int o = 4; o <= 16; o <<= 1) {
#pragma unroll
        for (int nt = 0; nt < 4; nt++) {
            Zl[nt][0] += __shfl_xor_sync(0xffffffffu, Zl[nt][0], o);
            Zl[nt][1] += __shfl_xor_sync(0xffffffffu, Zl[nt][1], o);
            Rl[nt][0] += __shfl_xor_sync(0xffffffffu, Rl[nt][0], o);
            Rl[nt][1] += __shfl_xor_sync(0xffffffffu, Rl[nt][1], o);
        }
    }
    if (lane < 4) {
#pragma unroll
        for (int nt = 0; nt < 4; nt++) {
            zs[warp * 32 + nt * 8 + 2 * lane + 0] = Zl[nt][0];
            zs[warp * 32 + nt * 8 + 2 * lane + 1] = Zl[nt][1];
            rs[warp * 32 + nt * 8 + 2 * lane + 0] = Rl[nt][0];
            rs[warp * 32 + nt * 8 + 2 * lane + 1] = Rl[nt][1];
        }
    }
    __syncthreads();

    // cross-warp combine + yhat + loss terms
    if (tid < YT) {
        float Z = 0.f, R = 0.f;
#pragma unroll
        for (int w = 0; w < 8; w++) { Z += zs[w * 32 + tid]; R += rs[w * 32 + tid]; }
        iZ_s[tid] = 1.f / Z;
        float lossterm = 0.f;
        int gy = y0t + tid;
        if (gy < Y_) {
            float r  = R / Z + final_b[gy];
            float yh = 1.f / (1.f + expf(-r));
            out_yhat[b * Y_ + gy] = yh;
            float tg = target[b * Y_ + gy];
            lossterm = tg * logf(yh + 1e-12f) + (1.f - tg) * logf(1.f - yh + 1e-12f);
        }
        lt[tid] = lossterm;
    }
    __syncthreads();
    if (tid == 0) {
        float s = 0.f;
#pragma unroll
        for (int i = 0; i < YT; i++) s += lt[i];
        g_losspart[b * gridDim.x + blockIdx.x] = s;
    }

    // in-place rescale: warp w scales labels 4w..4w+3 (L2-hot, scalar accesses
    // since the alpha region is only 4-byte aligned)
    if (write_alpha) {
#pragma unroll
        for (int i = 0; i < 4; i++) {
            int yl = warp * 4 + i;
            int gy = y0t + yl;
            if (gy >= Y_) continue;
            float iZ = iZ_s[yl];
            float* ap = out_alpha + (arow0 + gy) * L_;
#pragma unroll 4
            for (int v = lane; v < L_; v += 32)
                ap[v] *= iZ;
        }
    }
}

// ---------------------------------------------------------------------------
// Kernel 3: deterministic loss reduction
// ---------------------------------------------------------------------------
__global__ void loss_kernel(float* __restrict__ out_loss, int npart)
{
    __shared__ float red[256];
    float s = 0.f;
    for (int i = threadIdx.x; i < npart; i += 256) s += g_losspart[i];
    red[threadIdx.x] = s;
    __syncthreads();
    for (int o = 128; o > 0; o >>= 1) {
        if (threadIdx.x < o) red[threadIdx.x] += red[threadIdx.x + o];
        __syncthreads();
    }
    if (threadIdx.x == 0) *out_loss = -red[0] / (float)(B_ * Y_);
}

// ---------------------------------------------------------------------------
extern "C" void kernel_launch(void* const* d_in, const int* in_sizes, int n_in,
                              void* d_out, int out_size)
{
    const int*   tokens  = (const int*)  d_in[0];
    const float* target  = (const float*)d_in[1];
    const float* embed_W = (const float*)d_in[2];
    const float* conv_w  = (const float*)d_in[3];
    const float* conv_b  = (const float*)d_in[4];
    const float* U_w     = (const float*)d_in[5];
    const float* final_w = (const float*)d_in[6];
    const float* final_b = (const float*)d_in[7];
    float* out = (float*)d_out;

    const long long yhat_n  = (long long)B_ * Y_;                 // 71368
    const long long total_n = yhat_n + 1 + (long long)B_ * Y_ * L_;
    int write_loss  = (out_size >= (int)(yhat_n + 1)) ? 1 : 0;
    int write_alpha = ((long long)out_size >= total_n) ? 1 : 0;

    const int smem_bytes = 2 * (NK * 4 * 32) * 16        // wS4 + wQ4
                         + (LCH * FP) * 4                // h chunk
                         + (8 * 32 * 2 + YT + YT) * 4;   // zs, rs, iZ, lt
    cudaFuncSetAttribute(attn_kernel, cudaFuncAttributeMaxDynamicSharedMemorySize,
                         smem_bytes);

    conv_kernel<<<dim3(L_ / 64, B_), 256>>>(tokens, embed_W, conv_w, conv_b);
    transpose_kernel<<<dim3(L_ / 256, B_), 256>>>();

    float* out_alpha = out + yhat_n + 1;
    attn_kernel<<<dim3(NYT, B_), 256, smem_bytes>>>(
        U_w, final_w, final_b, target, out, out_alpha, write_alpha);

    if (write_loss)
        loss_kernel<<<1, 256>>>(out + yhat_n, B_ * NYT);
}

// round 11
// speedup vs baseline: 1.5743x; 1.2218x over previous
#include <cuda_runtime.h>
#include <cuda_bf16.h>
#include <math.h>
#include <stdint.h>

#define B_  8
#define L_  2048
#define E_  100
#define FM_ 50
#define Y_  8921
#define K_  9

#define YT    32          // labels per attn block
#define NYT   279         // ceil(Y_/YT)
#define FPAIR 36          // padded bf16-pair row stride (64 f = 32 pairs + 4 pad)
#define LCH   256         // positions per chunk
#define NCHK  (L_ / LCH)  // 8
#define NKB   4           // k-steps of 16 covering f 0..63 (50 real + zero pad)

// scratch (static device arrays are allowed)
__device__ float    g_h  [(size_t)B_ * FM_ * L_];     // conv output [b][f][l]
__device__ uint32_t g_hhi[(size_t)B_ * L_ * FPAIR];   // bf16 hi pairs [b][l][36]
__device__ uint32_t g_hlo[(size_t)B_ * L_ * FPAIR];   // bf16 lo pairs
__device__ float    g_losspart[B_ * NYT];

// ---- bf16 helpers ----------------------------------------------------------
__device__ __forceinline__ uint32_t pack_bf2(__nv_bfloat16 a, __nv_bfloat16 b) {
    return (uint32_t)__bfloat16_as_ushort(a) |
           ((uint32_t)__bfloat16_as_ushort(b) << 16);
}
__device__ __forceinline__ void split_bf(float x, __nv_bfloat16& h, __nv_bfloat16& l) {
    h = __float2bfloat16(x);
    l = __float2bfloat16(x - __bfloat162float(h));
}
__device__ __forceinline__ void mma_bf16(float d[4], const uint32_t a[4],
                                         uint32_t b0, uint32_t b1) {
    asm("mma.sync.aligned.m16n8k16.row.col.f32.bf16.bf16.f32 "
        "{%0,%1,%2,%3},{%4,%5,%6,%7},{%8,%9},{%0,%1,%2,%3};"
        : "+f"(d[0]), "+f"(d[1]), "+f"(d[2]), "+f"(d[3])
        : "r"(a[0]), "r"(a[1]), "r"(a[2]), "r"(a[3]), "r"(b0), "r"(b1));
}

// ---------------------------------------------------------------------------
// Kernel 1: embedding gather + conv1d(K=9, same) + bias + tanh -> g_h[b][f][l]
// (unchanged, proven)
// ---------------------------------------------------------------------------
__global__ void __launch_bounds__(256) conv_kernel(
    const int* __restrict__ tokens,
    const float* __restrict__ embed_W,
    const float* __restrict__ conv_w,
    const float* __restrict__ conv_b)
{
    __shared__ int   tok_s[72];
    __shared__ float x_s[72][21];
    __shared__ float w_s[50][20][9];

    const int tid   = threadIdx.x;
    const int b     = blockIdx.y;
    const int lbase = blockIdx.x * 64;

    if (tid < 72) {
        int gl = lbase + tid - 4;
        tok_s[tid] = (gl >= 0 && gl < L_) ? tokens[b * L_ + gl] : -1;
    }
    __syncthreads();

    const int f  = tid >> 2;
    const int lg = tid & 3;
    const int l0 = lg * 16;

    float acc[16];
#pragma unroll
    for (int j = 0; j < 16; j++) acc[j] = 0.f;

    for (int ec = 0; ec < 5; ec++) {
        for (int idx = tid; idx < 72 * 20; idx += 256) {
            int i = idx / 20, e = idx % 20;
            int t = tok_s[i];
            x_s[i][e] = (t >= 0) ? embed_W[(size_t)t * E_ + ec * 20 + e] : 0.f;
        }
        for (int idx = tid; idx < 50 * 20 * 9; idx += 256) {
            int ff = idx / 180, r = idx % 180;
            w_s[ff][r / 9][r % 9] = conv_w[ff * (E_ * K_) + ec * 180 + r];
        }
        __syncthreads();

        if (f < FM_) {
            for (int e = 0; e < 20; e++) {
                float xv[24];
#pragma unroll
                for (int t = 0; t < 24; t++) xv[t] = x_s[l0 + t][e];
                float wv[9];
#pragma unroll
                for (int k = 0; k < 9; k++) wv[k] = w_s[f][e][k];
#pragma unroll
                for (int k = 0; k < 9; k++)
#pragma unroll
                    for (int j = 0; j < 16; j++)
                        acc[j] += xv[j + k] * wv[k];
            }
        }
        __syncthreads();
    }

    if (f < FM_) {
        float bias = conv_b[f];
#pragma unroll
        for (int j = 0; j < 16; j++) {
            int l = lbase + l0 + j;
            g_h[((size_t)(b * FM_) + f) * L_ + l] = tanhf(acc[j] + bias);
        }
    }
}

// ---------------------------------------------------------------------------
// Kernel 1b: transpose + bf16 hi/lo split: g_h[b][f][l] -> pair planes
// g_hhi/g_hlo[b][l][p], pair p = (f=2p, f=2p+1), zero-pad f>=50 and p>=32.
// ---------------------------------------------------------------------------
__global__ void __launch_bounds__(256) transpose_kernel()
{
    const int b = blockIdx.y;
    const int l = blockIdx.x * 256 + threadIdx.x;
    const float* src = g_h + (size_t)b * FM_ * L_;
    uint32_t* dhi = g_hhi + ((size_t)b * L_ + l) * FPAIR;
    uint32_t* dlo = g_hlo + ((size_t)b * L_ + l) * FPAIR;
#pragma unroll 4
    for (int p = 0; p < FPAIR; p++) {
        int f0 = 2 * p, f1 = 2 * p + 1;
        float x0 = (f0 < FM_) ? src[(size_t)f0 * L_ + l] : 0.f;
        float x1 = (f1 < FM_) ? src[(size_t)f1 * L_ + l] : 0.f;
        __nv_bfloat16 h0, l0b, h1, l1b;
        split_bf(x0, h0, l0b);
        split_bf(x1, h1, l1b);
        dhi[p] = pack_bf2(h0, h1);
        dlo[p] = pack_bf2(l0b, l1b);
    }
}

// ---------------------------------------------------------------------------
// Kernel 2: label attention via 3-term bf16 mma.sync m16n8k16.
// block = (32 labels, b), 256 threads = 8 warps, 2 CTAs/SM.
// Chunk = 256 positions in smem (hi/lo planes, pair stride FPAIR=36 ->
// conflict-free: bank = 4g+t covers all 32). Warp owns positions
// [32w,32w+32) = 2 M-tiles. 4 N-tiles of 8 labels. K: 4 steps of 16.
// S,Q each = ah*bh + ah*bl + al*bh (dropped al*bl ~2^-16 rel).
// Weights pre-split hi/lo in fragment order: one uint4/lane per (k,nt,gemm)
// = {bhi0,bhi1,blo0,blo1}. Acc layout c0=(g,2t) c1=(g,2t+1) c2=(g+8,2t) c3,
// epilogue/Z/R/rescale identical to the proven round-10 kernel.
// ---------------------------------------------------------------------------
__global__ void __launch_bounds__(256, 2) attn_kernel(
    const float* __restrict__ U_w,
    const float* __restrict__ final_w,
    const float* __restrict__ final_b,
    const float* __restrict__ target,
    float* __restrict__ out_yhat,
    float* __restrict__ out_alpha,
    int write_alpha)
{
    extern __shared__ __align__(16) unsigned char smraw[];
    uint4*    wS   = (uint4*)smraw;                    // [NKB*4*32] 8192 B
    uint4*    wQ   = wS + NKB * 4 * 32;                // 8192 B
    uint32_t* smhi = (uint32_t*)(wQ + NKB * 4 * 32);   // [LCH*FPAIR] 36864 B
    uint32_t* smlo = smhi + LCH * FPAIR;               // 36864 B
    float*    zs   = (float*)(smlo + LCH * FPAIR);     // [8*32]
    float*    rs   = zs + 8 * 32;                      // [8*32]
    float*    iZ_s = rs + 8 * 32;                      // [32]
    float*    lt   = iZ_s + YT;                        // [32]

    const int tid  = threadIdx.x;
    const int lane = tid & 31;
    const int warp = tid >> 5;
    const int b    = blockIdx.y;
    const int y0t  = blockIdx.x * YT;

    const int g = lane >> 2;       // mma groupID (0..7)
    const int t = lane & 3;        // mma thread-in-group (0..3)

    // ---- build fragment-order hi/lo bf16 weights ----
    // entry (k,nt,lane): B col n = g (label nt*8+g); rows k*16 + {2t,2t+1}
    // (reg0) and k*16 + {2t+8,2t+9} (reg1).
    for (int idx = tid; idx < NKB * 4 * 32; idx += 256) {
        int k  = idx >> 7;
        int nt = (idx >> 5) & 3;
        int ln = idx & 31;
        int gg = ln >> 2, tt = ln & 3;
        int gy = y0t + nt * 8 + gg;
        int f00 = k * 16 + 2 * tt, f01 = f00 + 1;
        int f10 = f00 + 8,         f11 = f10 + 1;
        float u00=0.f,u01=0.f,u10=0.f,u11=0.f, v00=0.f,v01=0.f,v10=0.f,v11=0.f;
        if (gy < Y_) {
            const float* up = U_w    + gy * FM_;
            const float* vp = final_w + gy * FM_;
            if (f00 < FM_) { u00 = up[f00]; v00 = vp[f00]; }
            if (f01 < FM_) { u01 = up[f01]; v01 = vp[f01]; }
            if (f10 < FM_) { u10 = up[f10]; v10 = vp[f10]; }
            if (f11 < FM_) { u11 = up[f11]; v11 = vp[f11]; }
        }
        __nv_bfloat16 h00,l00,h01,l01,h10,l10,h11,l11;
        split_bf(u00,h00,l00); split_bf(u01,h01,l01);
        split_bf(u10,h10,l10); split_bf(u11,h11,l11);
        wS[idx] = make_uint4(pack_bf2(h00,h01), pack_bf2(h10,h11),
                             pack_bf2(l00,l01), pack_bf2(l10,l11));
        split_bf(v00,h00,l00); split_bf(v01,h01,l01);
        split_bf(v10,h10,l10); split_bf(v11,h11,l11);
        wQ[idx] = make_uint4(pack_bf2(h00,h01), pack_bf2(h10,h11),
                             pack_bf2(l00,l01), pack_bf2(l10,l11));
    }

    // lane-local Z,R: label = nt*8 + 2t + p
    float Zl[4][2] = {{0.f,0.f},{0.f,0.f},{0.f,0.f},{0.f,0.f}};
    float Rl[4][2] = {{0.f,0.f},{0.f,0.f},{0.f,0.f},{0.f,0.f}};

    const size_t arow0 = (size_t)b * Y_;
    const int prow0 = warp * 32;   // warp's first position row within chunk

    for (int ch = 0; ch < NCHK; ch++) {
        __syncthreads();   // previous chunk readers done (covers weight build)
        {   // stage both planes: contiguous, uint4
            const uint4* shi = (const uint4*)(g_hhi +
                ((size_t)b * L_ + (size_t)ch * LCH) * FPAIR);
            const uint4* slo = (const uint4*)(g_hlo +
                ((size_t)b * L_ + (size_t)ch * LCH) * FPAIR);
            uint4* dhi = (uint4*)smhi;
            uint4* dlo = (uint4*)smlo;
#pragma unroll
            for (int i = tid; i < LCH * FPAIR / 4; i += 256) {
                dhi[i] = shi[i];
                dlo[i] = slo[i];
            }
        }
        __syncthreads();

        float accS[2][4][4] = {};
        float accQ[2][4][4] = {};

#pragma unroll
        for (int k = 0; k < NKB; k++) {
            uint32_t ahi[2][4], alo[2][4];
#pragma unroll
            for (int mt = 0; mt < 2; mt++) {
                const int r0 = prow0 + mt * 16;
                const int pa = k * 8 + t;
                ahi[mt][0] = smhi[(r0 + g)     * FPAIR + pa];
                ahi[mt][1] = smhi[(r0 + g + 8) * FPAIR + pa];
                ahi[mt][2] = smhi[(r0 + g)     * FPAIR + pa + 4];
                ahi[mt][3] = smhi[(r0 + g + 8) * FPAIR + pa + 4];
                alo[mt][0] = smlo[(r0 + g)     * FPAIR + pa];
                alo[mt][1] = smlo[(r0 + g + 8) * FPAIR + pa];
                alo[mt][2] = smlo[(r0 + g)     * FPAIR + pa + 4];
                alo[mt][3] = smlo[(r0 + g + 8) * FPAIR + pa + 4];
            }
#pragma unroll
            for (int nt = 0; nt < 4; nt++) {
                uint4 Bs = wS[(k * 4 + nt) * 32 + lane];
                uint4 Bq = wQ[(k * 4 + nt) * 32 + lane];
#pragma unroll
                for (int mt = 0; mt < 2; mt++) {
                    mma_bf16(accS[mt][nt], ahi[mt], Bs.x, Bs.y);  // ah*bh
                    mma_bf16(accS[mt][nt], ahi[mt], Bs.z, Bs.w);  // ah*bl
                    mma_bf16(accS[mt][nt], alo[mt], Bs.x, Bs.y);  // al*bh
                    mma_bf16(accQ[mt][nt], ahi[mt], Bq.x, Bq.y);
                    mma_bf16(accQ[mt][nt], ahi[mt], Bq.z, Bq.w);
                    mma_bf16(accQ[mt][nt], alo[mt], Bq.x, Bq.y);
                }
            }
        }

        // per-chunk epilogue (identical to proven R10)
        const int chb = ch * LCH;
#pragma unroll
        for (int mt = 0; mt < 2; mt++) {
            const int posA = chb + prow0 + mt * 16 + g;
            const int posB = posA + 8;
#pragma unroll
            for (int nt = 0; nt < 4; nt++) {
                const int lab0 = y0t + nt * 8 + 2 * t;
                const int lab1 = lab0 + 1;
                float e0 = __expf(accS[mt][nt][0]);
                float e1 = __expf(accS[mt][nt][1]);
                float e2 = __expf(accS[mt][nt][2]);
                float e3 = __expf(accS[mt][nt][3]);
                Zl[nt][0] += e0 + e2;
                Zl[nt][1] += e1 + e3;
                Rl[nt][0] += e0 * accQ[mt][nt][0] + e2 * accQ[mt][nt][2];
                Rl[nt][1] += e1 * accQ[mt][nt][1] + e3 * accQ[mt][nt][3];
                if (write_alpha) {
                    if (lab0 < Y_) {
                        float* rp = out_alpha + (arow0 + lab0) * L_;
                        rp[posA] = e0; rp[posB] = e2;
                    }
                    if (lab1 < Y_) {
                        float* rp = out_alpha + (arow0 + lab1) * L_;
                        rp[posA] = e1; rp[posB] = e3;
                    }
                }
            }
        }
    }

    // reduce over g (lane bits 2,3,4)
#pragma unroll
    for (int o = 4; o <= 16; o <<= 1) {
#pragma unroll
        for (int nt = 0; nt < 4; nt++) {
            Zl[nt][0] += __shfl_xor_sync(0xffffffffu, Zl[nt][0], o);
            Zl[nt][1] += __shfl_xor_sync(0xffffffffu, Zl[nt][1], o);
            Rl[nt][0] += __shfl_xor_sync(0xffffffffu, Rl[nt][0], o);
            Rl[nt][1] += __shfl_xor_sync(0xffffffffu, Rl[nt][1], o);
        }
    }
    if (lane < 4) {
#pragma unroll
        for (int nt = 0; nt < 4; nt++) {
            zs[warp * 32 + nt * 8 + 2 * lane + 0] = Zl[nt][0];
            zs[warp * 32 + nt * 8 + 2 * lane + 1] = Zl[nt][1];
            rs[warp * 32 + nt * 8 + 2 * lane + 0] = Rl[nt][0];
            rs[warp * 32 + nt * 8 + 2 * lane + 1] = Rl[nt][1];
        }
    }
    __syncthreads();

    // cross-warp combine + yhat + loss terms
    if (tid < YT) {
        float Z = 0.f, R = 0.f;
#pragma unroll
        for (int w = 0; w < 8; w++) { Z += zs[w * 32 + tid]; R += rs[w * 32 + tid]; }
        iZ_s[tid] = 1.f / Z;
        float lossterm = 0.f;
        int gy = y0t + tid;
        if (gy < Y_) {
            float r  = R / Z + final_b[gy];
            float yh = 1.f / (1.f + expf(-r));
            out_yhat[b * Y_ + gy] = yh;
            float tg = target[b * Y_ + gy];
            lossterm = tg * logf(yh + 1e-12f) + (1.f - tg) * logf(1.f - yh + 1e-12f);
        }
        lt[tid] = lossterm;
    }
    __syncthreads();
    if (tid == 0) {
        float s = 0.f;
#pragma unroll
        for (int i = 0; i < YT; i++) s += lt[i];
        g_losspart[b * gridDim.x + blockIdx.x] = s;
    }

    // in-place rescale: warp w scales labels 4w..4w+3 (L2-hot, scalar stores —
    // alpha region is only 4-byte aligned)
    if (write_alpha) {
#pragma unroll
        for (int i = 0; i < 4; i++) {
            int yl = warp * 4 + i;
            int gy = y0t + yl;
            if (gy >= Y_) continue;
            float iZ = iZ_s[yl];
            float* ap = out_alpha + (arow0 + gy) * L_;
#pragma unroll 4
            for (int v = lane; v < L_; v += 32)
                ap[v] *= iZ;
        }
    }
}

// ---------------------------------------------------------------------------
// Kernel 3: deterministic loss reduction
// ---------------------------------------------------------------------------
__global__ void loss_kernel(float* __restrict__ out_loss, int npart)
{
    __shared__ float red[256];
    float s = 0.f;
    for (int i = threadIdx.x; i < npart; i += 256) s += g_losspart[i];
    red[threadIdx.x] = s;
    __syncthreads();
    for (int o = 128; o > 0; o >>= 1) {
        if (threadIdx.x < o) red[threadIdx.x] += red[threadIdx.x + o];
        __syncthreads();
    }
    if (threadIdx.x == 0) *out_loss = -red[0] / (float)(B_ * Y_);
}

// ---------------------------------------------------------------------------
extern "C" void kernel_launch(void* const* d_in, const int* in_sizes, int n_in,
                              void* d_out, int out_size)
{
    const int*   tokens  = (const int*)  d_in[0];
    const float* target  = (const float*)d_in[1];
    const float* embed_W = (const float*)d_in[2];
    const float* conv_w  = (const float*)d_in[3];
    const float* conv_b  = (const float*)d_in[4];
    const float* U_w     = (const float*)d_in[5];
    const float* final_w = (const float*)d_in[6];
    const float* final_b = (const float*)d_in[7];
    float* out = (float*)d_out;

    const long long yhat_n  = (long long)B_ * Y_;                 // 71368
    const long long total_n = yhat_n + 1 + (long long)B_ * Y_ * L_;
    int write_loss  = (out_size >= (int)(yhat_n + 1)) ? 1 : 0;
    int write_alpha = ((long long)out_size >= total_n) ? 1 : 0;

    const int smem_bytes = 2 * (NKB * 4 * 32) * 16       // wS + wQ
                         + 2 * (LCH * FPAIR) * 4         // hi/lo planes
                         + (8 * 32 * 2 + YT + YT) * 4;   // zs, rs, iZ, lt
    cudaFuncSetAttribute(attn_kernel, cudaFuncAttributeMaxDynamicSharedMemorySize,
                         smem_bytes);

    conv_kernel<<<dim3(L_ / 64, B_), 256>>>(tokens, embed_W, conv_w, conv_b);
    transpose_kernel<<<dim3(L_ / 256, B_), 256>>>();

    float* out_alpha = out + yhat_n + 1;
    attn_kernel<<<dim3(NYT, B_), 256, smem_bytes>>>(
        U_w, final_w, final_b, target, out, out_alpha, write_alpha);

    if (write_loss)
        loss_kernel<<<1, 256>>>(out + yhat_n, B_ * NYT);
}

// round 13
// speedup vs baseline: 1.7107x; 1.0867x over previous
#include <cuda_runtime.h>
#include <cuda_bf16.h>
#include <math.h>
#include <stdint.h>

#define B_  8
#define L_  2048
#define E_  100
#define FM_ 50
#define Y_  8921
#define K_  9

#define YT    32          // labels per attn block
#define NYT   279         // ceil(Y_/YT)
#define FPAIR 28          // bf16-pair row stride (24 real pairs + 4 pad)
#define LCH   256         // positions per chunk
#define NCHK  (L_ / LCH)  // 8
#define NKB   3           // k-steps of 16 covering f 0..47; f 48,49 via fp32 fixup
#define LOG2E 1.4426950408889634f

// scratch (static device arrays are allowed)
__device__ uint32_t g_hhi[(size_t)B_ * L_ * FPAIR];   // bf16 hi pairs [b][l][28]
__device__ uint32_t g_hlo[(size_t)B_ * L_ * FPAIR];   // bf16 lo pairs
__device__ float    g_h2 [(size_t)B_ * L_ * 2];       // fp32 h for f=48,49
__device__ float    g_losspart[B_ * NYT];

// ---- bf16 helpers ----------------------------------------------------------
__device__ __forceinline__ uint32_t pack_bf2(__nv_bfloat16 a, __nv_bfloat16 b) {
    return (uint32_t)__bfloat16_as_ushort(a) |
           ((uint32_t)__bfloat16_as_ushort(b) << 16);
}
__device__ __forceinline__ void split_bf(float x, __nv_bfloat16& h, __nv_bfloat16& l) {
    h = __float2bfloat16(x);
    l = __float2bfloat16(x - __bfloat162float(h));
}
__device__ __forceinline__ void mma_bf16(float d[4], const uint32_t a[4],
                                         uint32_t b0, uint32_t b1) {
    asm("mma.sync.aligned.m16n8k16.row.col.f32.bf16.bf16.f32 "
        "{%0,%1,%2,%3},{%4,%5,%6,%7},{%8,%9},{%0,%1,%2,%3};"
        : "+f"(d[0]), "+f"(d[1]), "+f"(d[2]), "+f"(d[3])
        : "r"(a[0]), "r"(a[1]), "r"(a[2]), "r"(a[3]), "r"(b0), "r"(b1));
}

// ---------------------------------------------------------------------------
// Kernel 1: embed + conv1d(K=9) + bias + tanh.
// f 0..47 -> bf16 hi/lo pair planes [b][l][28] (ushort offset (b*L+l)*56 + f);
// f 48,49 -> fp32 g_h2. Pad pairs 24..27 never feed the MMA (stride pad only).
// ---------------------------------------------------------------------------
__global__ void __launch_bounds__(256) conv_kernel(
    const int* __restrict__ tokens,
    const float* __restrict__ embed_W,
    const float* __restrict__ conv_w,
    const float* __restrict__ conv_b)
{
    __shared__ int   tok_s[72];
    __shared__ float x_s[72][21];
    __shared__ float w_s[50][20][9];

    const int tid   = threadIdx.x;
    const int b     = blockIdx.y;
    const int lbase = blockIdx.x * 64;

    if (tid < 72) {
        int gl = lbase + tid - 4;
        tok_s[tid] = (gl >= 0 && gl < L_) ? tokens[b * L_ + gl] : -1;
    }
    __syncthreads();

    const int f  = tid >> 2;
    const int lg = tid & 3;
    const int l0 = lg * 16;

    float acc[16];
#pragma unroll
    for (int j = 0; j < 16; j++) acc[j] = 0.f;

    for (int ec = 0; ec < 5; ec++) {
        for (int idx = tid; idx < 72 * 20; idx += 256) {
            int i = idx / 20, e = idx % 20;
            int t = tok_s[i];
            x_s[i][e] = (t >= 0) ? embed_W[(size_t)t * E_ + ec * 20 + e] : 0.f;
        }
        for (int idx = tid; idx < 50 * 20 * 9; idx += 256) {
            int ff = idx / 180, r = idx % 180;
            w_s[ff][r / 9][r % 9] = conv_w[ff * (E_ * K_) + ec * 180 + r];
        }
        __syncthreads();

        if (f < FM_) {
            for (int e = 0; e < 20; e++) {
                float xv[24];
#pragma unroll
                for (int t = 0; t < 24; t++) xv[t] = x_s[l0 + t][e];
                float wv[9];
#pragma unroll
                for (int k = 0; k < 9; k++) wv[k] = w_s[f][e][k];
#pragma unroll
                for (int k = 0; k < 9; k++)
#pragma unroll
                    for (int j = 0; j < 16; j++)
                        acc[j] += xv[j + k] * wv[k];
            }
        }
        __syncthreads();
    }

    if (f < FM_) {
        const float bias = conv_b[f];
        unsigned short* phi = (unsigned short*)g_hhi;
        unsigned short* plo = (unsigned short*)g_hlo;
#pragma unroll
        for (int j = 0; j < 16; j++) {
            int l = lbase + l0 + j;
            float v = tanhf(acc[j] + bias);
            if (f < 48) {
                __nv_bfloat16 hb, lb;
                split_bf(v, hb, lb);
                size_t o = ((size_t)b * L_ + l) * (2 * FPAIR) + f;
                phi[o] = __bfloat16_as_ushort(hb);
                plo[o] = __bfloat16_as_ushort(lb);
            } else {
                g_h2[((size_t)b * L_ + l) * 2 + (f - 48)] = v;
            }
        }
    }
}

// ---------------------------------------------------------------------------
// Kernel 2: label attention via 3-term bf16 mma.sync m16n8k16 (K=48) +
// exact fp32 fixup for f=48,49. U weights pre-scaled by log2e -> exp2f.
// block = (32 labels, b), 256 threads = 8 warps, 2 CTAs/SM.
// Structure identical to the proven R11 kernel otherwise.
// ---------------------------------------------------------------------------
__global__ void __launch_bounds__(256, 2) attn_kernel(
    const float* __restrict__ U_w,
    const float* __restrict__ final_w,
    const float* __restrict__ final_b,
    const float* __restrict__ target,
    float* __restrict__ out_yhat,
    float* __restrict__ out_alpha,
    int write_alpha)
{
    extern __shared__ __align__(16) unsigned char smraw[];
    uint4*    wS   = (uint4*)smraw;                    // [NKB*4*32] 6144 B
    uint4*    wQ   = wS + NKB * 4 * 32;                // 6144 B
    uint32_t* smhi = (uint32_t*)(wQ + NKB * 4 * 32);   // [LCH*FPAIR] 28672 B
    uint32_t* smlo = smhi + LCH * FPAIR;               // 28672 B
    float*    h2s  = (float*)(smlo + LCH * FPAIR);     // [LCH*2] 2048 B
    float4*   w2s  = (float4*)(h2s + LCH * 2);         // [32] 512 B
    float*    zs   = (float*)(w2s + 32);               // [8*32]
    float*    rs   = zs + 8 * 32;                      // [8*32]
    float*    iZ_s = rs + 8 * 32;                      // [32]
    float*    lt   = iZ_s + YT;                        // [32]

    const int tid  = threadIdx.x;
    const int lane = tid & 31;
    const int warp = tid >> 5;
    const int b    = blockIdx.y;
    const int y0t  = blockIdx.x * YT;

    const int g = lane >> 2;       // mma groupID (0..7)
    const int t = lane & 3;        // mma thread-in-group (0..3)

    // ---- fragment-order hi/lo bf16 weights for f 0..47 (U scaled by log2e)
    for (int idx = tid; idx < NKB * 4 * 32; idx += 256) {
        int k  = idx >> 7;
        int nt = (idx >> 5) & 3;
        int ln = idx & 31;
        int gg = ln >> 2, tt = ln & 3;
        int gy = y0t + nt * 8 + gg;
        int f00 = k * 16 + 2 * tt, f01 = f00 + 1;
        int f10 = f00 + 8,         f11 = f10 + 1;
        float u00=0.f,u01=0.f,u10=0.f,u11=0.f, v00=0.f,v01=0.f,v10=0.f,v11=0.f;
        if (gy < Y_) {
            const float* up = U_w     + gy * FM_;
            const float* vp = final_w + gy * FM_;
            u00 = up[f00] * LOG2E; v00 = vp[f00];
            u01 = up[f01] * LOG2E; v01 = vp[f01];
            u10 = up[f10] * LOG2E; v10 = vp[f10];
            u11 = up[f11] * LOG2E; v11 = vp[f11];
        }
        __nv_bfloat16 h00,l00,h01,l01,h10,l10,h11,l11;
        split_bf(u00,h00,l00); split_bf(u01,h01,l01);
        split_bf(u10,h10,l10); split_bf(u11,h11,l11);
        wS[idx] = make_uint4(pack_bf2(h00,h01), pack_bf2(h10,h11),
                             pack_bf2(l00,l01), pack_bf2(l10,l11));
        split_bf(v00,h00,l00); split_bf(v01,h01,l01);
        split_bf(v10,h10,l10); split_bf(v11,h11,l11);
        wQ[idx] = make_uint4(pack_bf2(h00,h01), pack_bf2(h10,h11),
                             pack_bf2(l00,l01), pack_bf2(l10,l11));
    }
    // fp32 fixup weights for f=48,49 (u's pre-scaled by log2e)
    if (tid < YT) {
        int gy = y0t + tid;
        float4 w = make_float4(0.f, 0.f, 0.f, 0.f);
        if (gy < Y_) {
            w.x = U_w[gy * FM_ + 48] * LOG2E;
            w.y = U_w[gy * FM_ + 49] * LOG2E;
            w.z = final_w[gy * FM_ + 48];
            w.w = final_w[gy * FM_ + 49];
        }
        w2s[tid] = w;
    }

    // lane-local Z,R: label = nt*8 + 2t + p
    float Zl[4][2] = {{0.f,0.f},{0.f,0.f},{0.f,0.f},{0.f,0.f}};
    float Rl[4][2] = {{0.f,0.f},{0.f,0.f},{0.f,0.f},{0.f,0.f}};

    const size_t arow0 = (size_t)b * Y_;
    const int prow0 = warp * 32;   // warp's first position row within chunk

    for (int ch = 0; ch < NCHK; ch++) {
        __syncthreads();   // previous chunk readers done (covers weight build)
        {   // stage both planes + h2: contiguous uint4/float4
            const uint4* shi = (const uint4*)(g_hhi +
                ((size_t)b * L_ + (size_t)ch * LCH) * FPAIR);
            const uint4* slo = (const uint4*)(g_hlo +
                ((size_t)b * L_ + (size_t)ch * LCH) * FPAIR);
            uint4* dhi = (uint4*)smhi;
            uint4* dlo = (uint4*)smlo;
#pragma unroll
            for (int i = tid; i < LCH * FPAIR / 4; i += 256) {
                dhi[i] = shi[i];
                dlo[i] = slo[i];
            }
            const float4* sh2 = (const float4*)(g_h2 +
                ((size_t)b * L_ + (size_t)ch * LCH) * 2);
            if (tid < LCH * 2 / 4) ((float4*)h2s)[tid] = sh2[tid];
        }
        __syncthreads();

        float accS[2][4][4] = {};
        float accQ[2][4][4] = {};

#pragma unroll
        for (int k = 0; k < NKB; k++) {
            uint32_t ahi[2][4], alo[2][4];
#pragma unroll
            for (int mt = 0; mt < 2; mt++) {
                const int r0 = prow0 + mt * 16;
                const int pa = k * 8 + t;
                ahi[mt][0] = smhi[(r0 + g)     * FPAIR + pa];
                ahi[mt][1] = smhi[(r0 + g + 8) * FPAIR + pa];
                ahi[mt][2] = smhi[(r0 + g)     * FPAIR + pa + 4];
                ahi[mt][3] = smhi[(r0 + g + 8) * FPAIR + pa + 4];
                alo[mt][0] = smlo[(r0 + g)     * FPAIR + pa];
                alo[mt][1] = smlo[(r0 + g + 8) * FPAIR + pa];
                alo[mt][2] = smlo[(r0 + g)     * FPAIR + pa + 4];
                alo[mt][3] = smlo[(r0 + g + 8) * FPAIR + pa + 4];
            }
#pragma unroll
            for (int nt = 0; nt < 4; nt++) {
                uint4 Bs = wS[(k * 4 + nt) * 32 + lane];
                uint4 Bq = wQ[(k * 4 + nt) * 32 + lane];
#pragma unroll
                for (int mt = 0; mt < 2; mt++) {
                    mma_bf16(accS[mt][nt], ahi[mt], Bs.x, Bs.y);  // ah*bh
                    mma_bf16(accS[mt][nt], ahi[mt], Bs.z, Bs.w);  // ah*bl
                    mma_bf16(accS[mt][nt], alo[mt], Bs.x, Bs.y);  // al*bh
                    mma_bf16(accQ[mt][nt], ahi[mt], Bq.x, Bq.y);
                    mma_bf16(accQ[mt][nt], ahi[mt], Bq.z, Bq.w);
                    mma_bf16(accQ[mt][nt], alo[mt], Bq.x, Bq.y);
                }
            }
        }

        // exact fp32 fixup for features 48,49
#pragma unroll
        for (int mt = 0; mt < 2; mt++) {
            const int pA = prow0 + mt * 16 + g;
            float hA0 = h2s[pA * 2],       hA1 = h2s[pA * 2 + 1];
            float hB0 = h2s[(pA + 8) * 2], hB1 = h2s[(pA + 8) * 2 + 1];
#pragma unroll
            for (int nt = 0; nt < 4; nt++) {
                float4 wa = w2s[nt * 8 + 2 * t];
                float4 wb = w2s[nt * 8 + 2 * t + 1];
                accS[mt][nt][0] += hA0 * wa.x + hA1 * wa.y;
                accS[mt][nt][1] += hA0 * wb.x + hA1 * wb.y;
                accS[mt][nt][2] += hB0 * wa.x + hB1 * wa.y;
                accS[mt][nt][3] += hB0 * wb.x + hB1 * wb.y;
                accQ[mt][nt][0] += hA0 * wa.z + hA1 * wa.w;
                accQ[mt][nt][1] += hA0 * wb.z + hA1 * wb.w;
                accQ[mt][nt][2] += hB0 * wa.z + hB1 * wa.w;
                accQ[mt][nt][3] += hB0 * wb.z + hB1 * wb.w;
            }
        }

        // per-chunk epilogue (e = exp2(s*log2e) = exp(s))
        const int chb = ch * LCH;
#pragma unroll
        for (int mt = 0; mt < 2; mt++) {
            const int posA = chb + prow0 + mt * 16 + g;
            const int posB = posA + 8;
#pragma unroll
            for (int nt = 0; nt < 4; nt++) {
                const int lab0 = y0t + nt * 8 + 2 * t;
                const int lab1 = lab0 + 1;
                float e0 = exp2f(accS[mt][nt][0]);
                float e1 = exp2f(accS[mt][nt][1]);
                float e2 = exp2f(accS[mt][nt][2]);
                float e3 = exp2f(accS[mt][nt][3]);
                Zl[nt][0] += e0 + e2;
                Zl[nt][1] += e1 + e3;
                Rl[nt][0] += e0 * accQ[mt][nt][0] + e2 * accQ[mt][nt][2];
                Rl[nt][1] += e1 * accQ[mt][nt][1] + e3 * accQ[mt][nt][3];
                if (write_alpha) {
                    if (lab0 < Y_) {
                        float* rp = out_alpha + (arow0 + lab0) * L_;
                        rp[posA] = e0; rp[posB] = e2;
                    }
                    if (lab1 < Y_) {
                        float* rp = out_alpha + (arow0 + lab1) * L_;
                        rp[posA] = e1; rp[posB] = e3;
                    }
                }
            }
        }
    }

    // reduce over g (lane bits 2,3,4)
#pragma unroll
    for (int o = 4; o <= 16; o <<= 1) {
#pragma unroll
        for (int nt = 0; nt < 4; nt++) {
            Zl[nt][0] += __shfl_xor_sync(0xffffffffu, Zl[nt][0], o);
            Zl[nt][1] += __shfl_xor_sync(0xffffffffu, Zl[nt][1], o);
            Rl[nt][0] += __shfl_xor_sync(0xffffffffu, Rl[nt][0], o);
            Rl[nt][1] += __shfl_xor_sync(0xffffffffu, Rl[nt][1], o);
        }
    }
    if (lane < 4) {
#pragma unroll
        for (int nt = 0; nt < 4; nt++) {
            zs[warp * 32 + nt * 8 + 2 * lane + 0] = Zl[nt][0];
            zs[warp * 32 + nt * 8 + 2 * lane + 1] = Zl[nt][1];
            rs[warp * 32 + nt * 8 + 2 * lane + 0] = Rl[nt][0];
            rs[warp * 32 + nt * 8 + 2 * lane + 1] = Rl[nt][1];
        }
    }
    __syncthreads();

    // cross-warp combine + yhat + loss terms
    if (tid < YT) {
        float Z = 0.f, R = 0.f;
#pragma unroll
        for (int w = 0; w < 8; w++) { Z += zs[w * 32 + tid]; R += rs[w * 32 + tid]; }
        iZ_s[tid] = 1.f / Z;
        float lossterm = 0.f;
        int gy = y0t + tid;
        if (gy < Y_) {
            float r  = R / Z + final_b[gy];
            float yh = 1.f / (1.f + expf(-r));
            out_yhat[b * Y_ + gy] = yh;
            float tg = target[b * Y_ + gy];
            lossterm = tg * logf(yh + 1e-12f) + (1.f - tg) * logf(1.f - yh + 1e-12f);
        }
        lt[tid] = lossterm;
    }
    __syncthreads();
    if (tid == 0) {
        float s = 0.f;
#pragma unroll
        for (int i = 0; i < YT; i++) s += lt[i];
        g_losspart[b * gridDim.x + blockIdx.x] = s;
    }

    // in-place rescale (L2-hot). Alpha region sits at odd float offset:
    // element c==3 (mod 4) of each row is 16B-aligned -> scalar head (0,1,2) +
    // 511 float4 + scalar tail (2047).
    if (write_alpha) {
#pragma unroll
        for (int i = 0; i < 4; i++) {
            int yl = warp * 4 + i;
            int gy = y0t + yl;
            if (gy >= Y_) continue;
            float iZ = iZ_s[yl];
            float* ap = out_alpha + (arow0 + gy) * L_;
            if (lane == 0) { ap[0] *= iZ; ap[1] *= iZ; ap[2] *= iZ; ap[2047] *= iZ; }
            float4* v = (float4*)(ap + 3);
#pragma unroll 4
            for (int j = lane; j < 511; j += 32) {
                float4 x = v[j];
                x.x *= iZ; x.y *= iZ; x.z *= iZ; x.w *= iZ;
                v[j] = x;
            }
        }
    }
}

// ---------------------------------------------------------------------------
// Kernel 3: deterministic loss reduction
// ---------------------------------------------------------------------------
__global__ void loss_kernel(float* __restrict__ out_loss, int npart)
{
    __shared__ float red[256];
    float s = 0.f;
    for (int i = threadIdx.x; i < npart; i += 256) s += g_losspart[i];
    red[threadIdx.x] = s;
    __syncthreads();
    for (int o = 128; o > 0; o >>= 1) {
        if (threadIdx.x < o) red[threadIdx.x] += red[threadIdx.x + o];
        __syncthreads();
    }
    if (threadIdx.x == 0) *out_loss = -red[0] / (float)(B_ * Y_);
}

// ---------------------------------------------------------------------------
extern "C" void kernel_launch(void* const* d_in, const int* in_sizes, int n_in,
                              void* d_out, int out_size)
{
    const int*   tokens  = (const int*)  d_in[0];
    const float* target  = (const float*)d_in[1];
    const float* embed_W = (const float*)d_in[2];
    const float* conv_w  = (const float*)d_in[3];
    const float* conv_b  = (const float*)d_in[4];
    const float* U_w     = (const float*)d_in[5];
    const float* final_w = (const float*)d_in[6];
    const float* final_b = (const float*)d_in[7];
    float* out = (float*)d_out;

    const long long yhat_n  = (long long)B_ * Y_;                 // 71368
    const long long total_n = yhat_n + 1 + (long long)B_ * Y_ * L_;
    int write_loss  = (out_size >= (int)(yhat_n + 1)) ? 1 : 0;
    int write_alpha = ((long long)out_size >= total_n) ? 1 : 0;

    const int smem_bytes = 2 * (NKB * 4 * 32) * 16       // wS + wQ
                         + 2 * (LCH * FPAIR) * 4         // hi/lo planes
                         + (LCH * 2) * 4                 // h2
                         + 32 * 16                       // w2
                         + (8 * 32 * 2 + YT + YT) * 4;   // zs, rs, iZ, lt
    cudaFuncSetAttribute(attn_kernel, cudaFuncAttributeMaxDynamicSharedMemorySize,
                         smem_bytes);

    conv_kernel<<<dim3(L_ / 64, B_), 256>>>(tokens, embed_W, conv_w, conv_b);

    float* out_alpha = out + yhat_n + 1;
    attn_kernel<<<dim3(NYT, B_), 256, smem_bytes>>>(
        U_w, final_w, final_b, target, out, out_alpha, write_alpha);

    if (write_loss)
        loss_kernel<<<1, 256>>>(out + yhat_n, B_ * NYT);
}